// round 13
// baseline (speedup 1.0000x reference)
#include <cuda_runtime.h>
#include <cuda_fp16.h>
#include <cstdint>

#define BB 8
#define TT 128
#define DD 512
#define MM (BB*TT)          // 1024 tokens
#define NWT 6
#define NN (NWT*DD)         // 3072 total output cols
#define KC 64
#define NCH (DD/KC)         // 8 chunks (pure fp16, K=512)
#define MT 128
#define NT 96
#define NCTA 256            // 8 x 32 tiles -> one wave at 2 CTAs/SM
#define NSTG 3
#define STG_BYTES (16384+12288)   // A 16KB + B(fp16) 12KB per stage
#define GSMEM (NSTG*STG_BYTES)
#define NB 8                // temporal buckets == warps per CTA (attn)
#define ND 6                // Taylor terms (degree 5)

__device__ float g_proj[NWT * MM * DD];
__device__ __half gA[(size_t)MM * DD];           // 1 MB  xh
__device__ unsigned int g_bar;                   // monotonic ticket barrier

struct WPtrs { const float* W[NWT]; const float* b[NWT]; };

// ---------------------------------------------------------------------------
__device__ __forceinline__ uint32_t smem_u32(const void* p) {
    uint32_t a;
    asm("{ .reg .u64 t; cvta.to.shared.u64 t, %1; cvt.u32.u64 %0, t; }" : "=r"(a) : "l"(p));
    return a;
}
__device__ __forceinline__ void cp16(uint32_t saddr, const void* g) {
    asm volatile("cp.async.cg.shared.global [%0], [%1], 16;" :: "r"(saddr), "l"(g));
}
__device__ __forceinline__ void cp_commit() { asm volatile("cp.async.commit_group;" ::: "memory"); }
__device__ __forceinline__ void cp_wait1()  { asm volatile("cp.async.wait_group 1;" ::: "memory"); }
__device__ __forceinline__ void ldsm4(uint32_t* d, uint32_t a) {
    asm volatile("ldmatrix.sync.aligned.m8n8.x4.shared.b16 {%0,%1,%2,%3}, [%4];"
        : "=r"(d[0]), "=r"(d[1]), "=r"(d[2]), "=r"(d[3]) : "r"(a));
}
__device__ __forceinline__ void mma16816(float* c, const uint32_t* a, uint32_t b0, uint32_t b1) {
    asm volatile(
        "mma.sync.aligned.m16n8k16.row.col.f32.f16.f16.f32 "
        "{%0,%1,%2,%3}, {%4,%5,%6,%7}, {%8,%9}, {%0,%1,%2,%3};"
        : "+f"(c[0]), "+f"(c[1]), "+f"(c[2]), "+f"(c[3])
        : "r"(a[0]), "r"(a[1]), "r"(a[2]), "r"(a[3]), "r"(b0), "r"(b1));
}
__device__ __forceinline__ float ex2f(float x) { float y; asm("ex2.approx.f32 %0, %1;" : "=f"(y) : "f"(x)); return y; }

#define SW128(o) ((o) ^ (((o) >> 3) & 0x70))

__device__ __forceinline__ uint4 cvt8(const float4 v0, const float4 v1) {
    __half2 h[4];
    h[0] = __floats2half2_rn(v0.x, v0.y);
    h[1] = __floats2half2_rn(v0.z, v0.w);
    h[2] = __floats2half2_rn(v1.x, v1.y);
    h[3] = __floats2half2_rn(v1.z, v1.w);
    return *(uint4*)h;
}

// Grid barrier: monotonic ticket counter (safe across graph replays).
// All 256 CTAs are co-resident (one wave) -> no deadlock.
__device__ __forceinline__ void grid_barrier(int tid) {
    __syncthreads();
    if (tid == 0) {
        __threadfence();                           // release my CTA's writes
        unsigned int ticket = atomicAdd(&g_bar, 1u);
        unsigned int target = ((ticket >> 8) + 1u) << 8;   // next multiple of 256
        while (*(volatile unsigned int*)&g_bar < target) { }
        __threadfence();                           // acquire
    }
    __syncthreads();
}

__device__ __forceinline__ void cpA(int tid, int m0, int c, uint32_t stg) {
    const int kb = c * KC;
    #pragma unroll
    for (int t = 0; t < 4; t++) {
        int idx = tid + t * 256;
        int row = idx >> 3, c16 = idx & 7;
        const char* ga = (const char*)gA + ((size_t)(m0 + row) * DD + kb) * 2 + c16 * 16;
        cp16(stg + SW128(row * 128 + c16 * 16), ga);
    }
    cp_commit();
}

// ---------------------------------------------------------------------------
// ONE persistent kernel: conv-x -> barrier -> gemm -> barrier -> attn x4
// ---------------------------------------------------------------------------
__global__ __launch_bounds__(256, 2) void fused_all(const float* __restrict__ x,
                                                    WPtrs p, float* __restrict__ out) {
    extern __shared__ __align__(1024) char dsm[];
    const uint32_t sbase = smem_u32(dsm);
    const int tid  = threadIdx.x;
    const int bid  = blockIdx.x;
    const int wid  = tid >> 5, lane = tid & 31;
    const float LOG2E = 1.4426950408889634f;

    // ---------------- gemm tile mapping + B pointers (needed for prefetch)
    const int m0 = (bid & 7) * MT;
    const int ng = (bid >> 3) * NT;
    const float* bsrc[3];
    int brow[3], bc8[3];
    #pragma unroll
    for (int j = 0; j < 3; j++) {
        int g = tid + j * 256;            // 768 groups: 96 rows x 8 col-groups
        brow[j] = g >> 3;
        bc8[j]  = g & 7;
        int n = ng + brow[j];
        bsrc[j] = p.W[n >> 9] + (size_t)(n & 511) * DD + bc8[j] * 8;
    }

    // prefetch B0 (cold DRAM) so its latency hides behind the conv phase
    float4 bv[6];
    #pragma unroll
    for (int j = 0; j < 3; j++) {
        bv[2*j]   = *(const float4*)(bsrc[j]);
        bv[2*j+1] = *(const float4*)(bsrc[j] + 4);
    }

    // ---------------- phase 0: conv x -> fp16 (65536 chunks of 8 floats)
    {
        const int chunk = bid * 256 + tid;
        const int m  = chunk >> 6;
        const int k8 = (chunk & 63) << 3;
        const float4 v0 = *(const float4*)&x[(size_t)m * DD + k8];
        const float4 v1 = *(const float4*)&x[(size_t)m * DD + k8 + 4];
        *(uint4*)&gA[(size_t)m * DD + k8] = cvt8(v0, v1);
    }
    grid_barrier(tid);

    // ---------------- phase 1: fp16 GEMM with fused W conversion
    float acc[2][6][4];
    #pragma unroll
    for (int i = 0; i < 2; i++)
        #pragma unroll
        for (int j = 0; j < 6; j++)
            #pragma unroll
            for (int q = 0; q < 4; q++) acc[i][j][q] = 0.f;

    cpA(tid, m0, 0, sbase);
    cpA(tid, m0, 1, sbase + STG_BYTES);
    #pragma unroll
    for (int j = 0; j < 3; j++)
        *(uint4*)(dsm + 16384 + SW128(brow[j] * 128 + bc8[j] * 16)) = cvt8(bv[2*j], bv[2*j+1]);
    #pragma unroll
    for (int j = 0; j < 3; j++) {
        bv[2*j]   = *(const float4*)(bsrc[j] + KC);
        bv[2*j+1] = *(const float4*)(bsrc[j] + KC + 4);
    }
    cp_wait1();           // A0 resident
    __syncthreads();      // B0 visible

    const int a_row  = (wid & 3) * 32 + (lane & 15);
    const int a_koff = ((lane >> 4) << 3) * 2;
    const int b_row  = (wid >> 2) * 48 + (lane & 7) + ((lane >> 4) << 3);
    const int b_koff = (((lane >> 3) & 1) << 3) * 2;

    int slot = 0;
    for (int ch = 0; ch < NCH; ch++) {
        if (ch + 2 < NCH) cpA(tid, m0, ch + 2, sbase + ((ch + 2) % 3) * STG_BYTES);
        else cp_commit();

        // STS B(ch+1) now (slot safe: held chunk ch-2), then start LDG B(ch+2)
        if (ch + 1 < NCH) {
            char* bdst = dsm + ((ch + 1) % 3) * STG_BYTES + 16384;
            #pragma unroll
            for (int j = 0; j < 3; j++)
                *(uint4*)(bdst + SW128(brow[j] * 128 + bc8[j] * 16)) = cvt8(bv[2*j], bv[2*j+1]);
            if (ch + 2 < NCH) {
                const int k = (ch + 2) * KC;
                #pragma unroll
                for (int j = 0; j < 3; j++) {
                    bv[2*j]   = *(const float4*)(bsrc[j] + k);
                    bv[2*j+1] = *(const float4*)(bsrc[j] + k + 4);
                }
            }
        }

        const uint32_t sAb = sbase + slot * STG_BYTES;
        const uint32_t sBb = sAb + 16384u;
        #pragma unroll
        for (int ks = 0; ks < 4; ks++) {
            const int kb = ks * 32;
            uint32_t a[2][4];
            #pragma unroll
            for (int mt = 0; mt < 2; mt++)
                ldsm4(a[mt], sAb + SW128((a_row + mt * 16) * 128 + kb + a_koff));
            uint32_t b[3][4];
            #pragma unroll
            for (int nt = 0; nt < 3; nt++)
                ldsm4(b[nt], sBb + SW128((b_row + nt * 16) * 128 + kb + b_koff));
            #pragma unroll
            for (int mt = 0; mt < 2; mt++)
                #pragma unroll
                for (int nb = 0; nb < 6; nb++)
                    mma16816(acc[mt][nb], a[mt], b[nb >> 1][(nb & 1) * 2], b[nb >> 1][(nb & 1) * 2 + 1]);
        }

        cp_wait1();
        __syncthreads();
        slot = (slot == 2) ? 0 : slot + 1;
    }

    // epilogue: + bias, write fp32 projections
    {
        const int qrow = lane >> 2;
        const int qcol = (lane & 3) * 2;
        #pragma unroll
        for (int mt = 0; mt < 2; mt++) {
            const int r0 = m0 + (wid & 3) * 32 + mt * 16 + qrow;
            #pragma unroll
            for (int nb = 0; nb < 6; nb++) {
                const int n  = ng + (wid >> 2) * 48 + nb * 8 + qcol;
                const int nw = n >> 9;
                const int no = n & 511;
                const float2 b2 = *(const float2*)&p.b[nw][no];
                float* d0 = &g_proj[((size_t)nw * MM + r0) * DD + no];
                float* d1 = &g_proj[((size_t)nw * MM + r0 + 8) * DD + no];
                ((float2*)d0)[0] = {acc[mt][nb][0] + b2.x, acc[mt][nb][1] + b2.y};
                ((float2*)d1)[0] = {acc[mt][nb][2] + b2.x, acc[mt][nb][3] + b2.y};
            }
        }
    }
    grid_barrier(tid);

    // ---------------- phase 2: attn, 4 tokens per CTA
    float* sK = (float*)dsm;
    float* sV = (float*)(dsm + 2048);
    float (*sMA)[8] = (float(*)[8])(dsm + 4096);
    float (*sMM)[8] = (float(*)[8])(dsm + 4096 + 256);
    float* redA = (float*)(dsm + 4608);
    float* redB = redA + 8;
    float* redC = redA + 16;

    for (int t = 0; t < 4; t++) {
        const int m = bid * 4 + t;
        const float* __restrict__ Qf = g_proj + (size_t)0 * MM * DD + (size_t)m * DD;
        const float* __restrict__ Kf = g_proj + (size_t)1 * MM * DD + (size_t)m * DD;
        const float* __restrict__ Vf = g_proj + (size_t)2 * MM * DD + (size_t)m * DD;
        const float* __restrict__ Qt = g_proj + (size_t)3 * MM * DD + (size_t)m * DD;
        const float* __restrict__ Kt = g_proj + (size_t)4 * MM * DD + (size_t)m * DD;
        const float* __restrict__ Vt = g_proj + (size_t)5 * MM * DD + (size_t)m * DD;

        const int i0 = tid, i1 = tid + 256;
        sK[i0] = Kt[i0]; sK[i1] = Kt[i1];
        sV[i0] = Vt[i0]; sV[i1] = Vt[i1];
        const float s0  = Qf[i0] * Kf[i0];
        const float s1  = Qf[i1] * Kf[i1];
        const float vf0 = Vf[i0], vf1 = Vf[i1];
        const float c0v = Qt[i0], c1v = Qt[i1];

        float smax = fmaxf(s0, s1), cmin = fminf(c0v, c1v), cmax = fmaxf(c0v, c1v);
        #pragma unroll
        for (int off = 16; off; off >>= 1) {
            smax = fmaxf(smax, __shfl_xor_sync(0xffffffffu, smax, off));
            cmin = fminf(cmin, __shfl_xor_sync(0xffffffffu, cmin, off));
            cmax = fmaxf(cmax, __shfl_xor_sync(0xffffffffu, cmax, off));
        }
        if (lane == 0) { redA[wid] = smax; redB[wid] = cmin; redC[wid] = cmax; }
        __syncthreads();   // also publishes sK / sV
        smax = redA[0]; cmin = redB[0]; cmax = redC[0];
        #pragma unroll
        for (int tt = 1; tt < 8; tt++) {
            smax = fmaxf(smax, redA[tt]);
            cmin = fminf(cmin, redB[tt]);
            cmax = fmaxf(cmax, redC[tt]);
        }
        __syncthreads();   // protect redA before reuse

        const float e0 = ex2f((s0 - smax) * LOG2E);
        const float e1 = ex2f((s1 - smax) * LOG2E);
        float zf = e0 + e1;
        #pragma unroll
        for (int off = 16; off; off >>= 1)
            zf += __shfl_xor_sync(0xffffffffu, zf, off);
        if (lane == 0) redA[wid] = zf;
        __syncthreads();
        zf = redA[0];
        #pragma unroll
        for (int tt = 1; tt < 8; tt++) zf += redA[tt];
        const float ctx_f0 = (e0 / zf) * vf0;
        const float ctx_f1 = (e1 / zf) * vf1;

        const float bw = (cmax - cmin) * (1.0f / NB);
        const float c0 = fmaf((float)wid + 0.5f, bw, cmin);
        const float c0l = c0 * LOG2E;

        float a1[ND], m1[ND], a2[ND], m2[ND];
        #pragma unroll
        for (int n = 0; n < ND; n++) { a1[n] = 0.f; m1[n] = 0.f; a2[n] = 0.f; m2[n] = 0.f; }

        #pragma unroll
        for (int jj = 0; jj < DD / 64; jj++) {
            const int j = jj * 64 + lane;
            const float ka = sK[j],      va = sV[j];
            const float kb = sK[j + 32], vb = sV[j + 32];
            float pa = ex2f(c0l * ka);
            float pb = ex2f(c0l * kb);
            #pragma unroll
            for (int n = 0; n < ND; n++) {
                a1[n] += pa;
                a2[n] += pb;
                m1[n]  = fmaf(pa, va, m1[n]);
                m2[n]  = fmaf(pb, vb, m2[n]);
                if (n < ND - 1) { pa *= ka; pb *= kb; }
            }
        }
        #pragma unroll
        for (int n = 0; n < ND; n++) {
            float av = a1[n] + a2[n], mv = m1[n] + m2[n];
            #pragma unroll
            for (int off = 16; off; off >>= 1) {
                av += __shfl_xor_sync(0xffffffffu, av, off);
                mv += __shfl_xor_sync(0xffffffffu, mv, off);
            }
            if (lane == 0) { sMA[wid][n] = av; sMM[wid][n] = mv; }
        }
        __syncthreads();

        const float Wd = cmax - cmin;
        const float sc = (Wd > 0.f) ? ((float)NB / Wd) : 0.f;
        const float IF[ND] = {1.f, 1.f, 0.5f, 1.f/6.f, 1.f/24.f, 1.f/120.f};

        #pragma unroll
        for (int item = 0; item < 2; item++) {
            const float c = item ? c1v : c0v;
            int b = (int)((c - cmin) * sc);
            b = (b > NB - 1) ? NB - 1 : ((b < 0) ? 0 : b);
            const float d = c - fmaf((float)b + 0.5f, bw, cmin);
            const float* MA  = sMA[b];
            const float* MMp = sMM[b];
            float den = MA[ND - 1] * IF[ND - 1];
            float num = MMp[ND - 1] * IF[ND - 1];
            #pragma unroll
            for (int n = ND - 2; n >= 0; n--) {
                den = fmaf(den, d, MA[n] * IF[n]);
                num = fmaf(num, d, MMp[n] * IF[n]);
            }
            const float ctx_f = item ? ctx_f1 : ctx_f0;
            out[(size_t)m * DD + (item ? i1 : i0)] = ctx_f + num / den;
        }
        __syncthreads();   // smem reuse safety before next token
    }
}

extern "C" void kernel_launch(void* const* d_in, const int* in_sizes, int n_in,
                              void* d_out, int out_size) {
    (void)in_sizes; (void)n_in; (void)out_size;
    const float* x = (const float*)d_in[0];
    WPtrs p;
    for (int w = 0; w < NWT; w++) {
        p.W[w] = (const float*)d_in[1 + 2 * w];
        p.b[w] = (const float*)d_in[2 + 2 * w];
    }
    cudaFuncSetAttribute(fused_all, cudaFuncAttributeMaxDynamicSharedMemorySize, GSMEM);
    fused_all<<<NCTA, 256, GSMEM>>>(x, p, (float*)d_out);
}

// round 14
// speedup vs baseline: 1.0709x; 1.0709x over previous
#include <cuda_runtime.h>
#include <cuda_fp16.h>
#include <cstdint>

#define BB 8
#define TT 128
#define DD 512
#define MM (BB*TT)          // 1024 tokens
#define NWT 6
#define NN (NWT*DD)         // 3072 total output cols
#define KC 64
#define NCH (DD/KC)         // 8 chunks (pure fp16, K=512)
#define MT 128
#define NT 96               // 8x32 = 256 CTAs -> one wave at 2 CTAs/SM
#define NB 8                // temporal buckets == warps per CTA (attn)
#define ND 6                // Taylor terms (degree 5)

// smem layout (per CTA): A fp16 x2, B fp32 staging x2, B fp16 x2
#define A_BYTES   16384     // 128 rows x 128B
#define B32_BYTES 24576     // 96 rows x 256B (fp32)
#define B16_BYTES 12288     // 96 rows x 128B (fp16)
#define OFF_A     0
#define OFF_B32   (2*A_BYTES)                 // 32768
#define OFF_B16   (OFF_B32 + 2*B32_BYTES)     // 81920
#define GSMEM     (OFF_B16 + 2*B16_BYTES)     // 106496 = 104 KB

__device__ float g_proj[NWT * MM * DD];
__device__ __half gA[(size_t)MM * DD];        // 1 MB  xh

struct WPtrs { const float* W[NWT]; const float* b[NWT]; };

// ---------------------------------------------------------------------------
__device__ __forceinline__ uint32_t smem_u32(const void* p) {
    uint32_t a;
    asm("{ .reg .u64 t; cvta.to.shared.u64 t, %1; cvt.u32.u64 %0, t; }" : "=r"(a) : "l"(p));
    return a;
}
__device__ __forceinline__ void cp16(uint32_t saddr, const void* g) {
    asm volatile("cp.async.cg.shared.global [%0], [%1], 16;" :: "r"(saddr), "l"(g));
}
__device__ __forceinline__ void cp_commit() { asm volatile("cp.async.commit_group;" ::: "memory"); }
__device__ __forceinline__ void cp_wait1()  { asm volatile("cp.async.wait_group 1;" ::: "memory"); }
__device__ __forceinline__ void ldsm4(uint32_t* d, uint32_t a) {
    asm volatile("ldmatrix.sync.aligned.m8n8.x4.shared.b16 {%0,%1,%2,%3}, [%4];"
        : "=r"(d[0]), "=r"(d[1]), "=r"(d[2]), "=r"(d[3]) : "r"(a));
}
__device__ __forceinline__ void mma16816(float* c, const uint32_t* a, uint32_t b0, uint32_t b1) {
    asm volatile(
        "mma.sync.aligned.m16n8k16.row.col.f32.f16.f16.f32 "
        "{%0,%1,%2,%3}, {%4,%5,%6,%7}, {%8,%9}, {%0,%1,%2,%3};"
        : "+f"(c[0]), "+f"(c[1]), "+f"(c[2]), "+f"(c[3])
        : "r"(a[0]), "r"(a[1]), "r"(a[2]), "r"(a[3]), "r"(b0), "r"(b1));
}
__device__ __forceinline__ float ex2f(float x) { float y; asm("ex2.approx.f32 %0, %1;" : "=f"(y) : "f"(x)); return y; }

#define SW128(o) ((o) ^ (((o) >> 3) & 0x70))

__device__ __forceinline__ uint4 cvt8(const float4 v0, const float4 v1) {
    __half2 h[4];
    h[0] = __floats2half2_rn(v0.x, v0.y);
    h[1] = __floats2half2_rn(v0.z, v0.w);
    h[2] = __floats2half2_rn(v1.x, v1.y);
    h[3] = __floats2half2_rn(v1.z, v1.w);
    return *(uint4*)h;
}

// ---------------------------------------------------------------------------
// conv: x only -> fp16 (W conversion happens inside the GEMM via cp.async)
// ---------------------------------------------------------------------------
__global__ __launch_bounds__(256) void conv_x(const float* __restrict__ x) {
    const int chunk = blockIdx.x * 256 + threadIdx.x;   // 65536 chunks of 8
    const int m  = chunk >> 6;
    const int k8 = (chunk & 63) << 3;
    const float4 v0 = *(const float4*)&x[(size_t)m * DD + k8];
    const float4 v1 = *(const float4*)&x[(size_t)m * DD + k8 + 4];
    *(uint4*)&gA[(size_t)m * DD + k8] = cvt8(v0, v1);
}

// ---------------------------------------------------------------------------
// GEMM: A fp16 via cp.async; B fp32 via cp.async staging -> smem convert.
// CTA tile 128x96, 2-stage rings, 256 CTAs = one wave at 2 CTAs/SM.
// ---------------------------------------------------------------------------
__global__ __launch_bounds__(256, 2) void gemm_mma(WPtrs p) {
    extern __shared__ __align__(1024) char dsm[];
    const uint32_t sbase = smem_u32(dsm);

    const int tid  = threadIdx.x;
    const int wid  = tid >> 5, lane = tid & 31;
    const int m0 = blockIdx.x * MT;
    const int ng = blockIdx.y * NT;

    // ---- B fp32 cp.async mapping: seg = tid&15 (16B within 256B row),
    //      rows r0+16t for t=0..5  (96 rows total)
    const int seg = tid & 15;
    const int r0  = tid >> 4;          // 0..15
    const float* wsrc[6];
    #pragma unroll
    for (int t = 0; t < 6; t++) {
        const int n = ng + r0 + 16 * t;
        wsrc[t] = p.W[n >> 9] + (size_t)(n & 511) * DD + seg * 4;
    }

    // ---- convert mapping: 3 groups per thread (768 = 96 rows x 8 col-groups)
    int brow[3], bc8[3];
    #pragma unroll
    for (int j = 0; j < 3; j++) {
        const int g = tid + j * 256;
        brow[j] = g >> 3;
        bc8[j]  = g & 7;
    }

    float acc[2][6][4];
    #pragma unroll
    for (int i = 0; i < 2; i++)
        #pragma unroll
        for (int j = 0; j < 6; j++)
            #pragma unroll
            for (int q = 0; q < 4; q++) acc[i][j][q] = 0.f;

    // group issue: A(ch) + B32(ch) together, one commit per group
    auto issue_group = [&](int ch) {
        const int s  = ch & 1;
        const int kb = ch * KC;
        const uint32_t aDst = sbase + OFF_A + s * A_BYTES;
        #pragma unroll
        for (int t = 0; t < 4; t++) {
            int idx = tid + t * 256;
            int row = idx >> 3, c16 = idx & 7;
            const char* ga = (const char*)gA + ((size_t)(m0 + row) * DD + kb) * 2 + c16 * 16;
            cp16(aDst + SW128(row * 128 + c16 * 16), ga);
        }
        const uint32_t bDst = sbase + OFF_B32 + s * B32_BYTES;
        #pragma unroll
        for (int t = 0; t < 6; t++) {
            const int row = r0 + 16 * t;
            cp16(bDst + row * 256 + seg * 16, wsrc[t] + kb);
        }
        cp_commit();
    };

    issue_group(0);
    issue_group(1);

    const int a_row  = (wid & 3) * 32 + (lane & 15);
    const int a_koff = ((lane >> 4) << 3) * 2;
    const int b_row  = (wid >> 2) * 48 + (lane & 7) + ((lane >> 4) << 3);
    const int b_koff = (((lane >> 3) & 1) << 3) * 2;

    for (int ch = 0; ch < NCH; ch++) {
        const int s = ch & 1;
        cp_wait1();            // group ch resident (group ch+1 in flight)
        __syncthreads();       // all warps see A(ch)/B32(ch); B16 slot s free

        // convert B32(ch) -> B16(ch) in smem
        {
            const char* src = dsm + OFF_B32 + s * B32_BYTES;
            char*       dst = dsm + OFF_B16 + s * B16_BYTES;
            #pragma unroll
            for (int j = 0; j < 3; j++) {
                const float4 v0 = *(const float4*)(src + brow[j] * 256 + bc8[j] * 32);
                const float4 v1 = *(const float4*)(src + brow[j] * 256 + bc8[j] * 32 + 16);
                *(uint4*)(dst + SW128(brow[j] * 128 + bc8[j] * 16)) = cvt8(v0, v1);
            }
        }
        __syncthreads();       // B16(ch) visible to all warps

        // compute chunk ch
        const uint32_t sAb = sbase + OFF_A  + s * A_BYTES;
        const uint32_t sBb = sbase + OFF_B16 + s * B16_BYTES;
        #pragma unroll
        for (int ks = 0; ks < 4; ks++) {
            const int kb = ks * 32;
            uint32_t a[2][4];
            #pragma unroll
            for (int mt = 0; mt < 2; mt++)
                ldsm4(a[mt], sAb + SW128((a_row + mt * 16) * 128 + kb + a_koff));
            uint32_t b[3][4];
            #pragma unroll
            for (int nt = 0; nt < 3; nt++)
                ldsm4(b[nt], sBb + SW128((b_row + nt * 16) * 128 + kb + b_koff));
            #pragma unroll
            for (int mt = 0; mt < 2; mt++)
                #pragma unroll
                for (int nb = 0; nb < 6; nb++)
                    mma16816(acc[mt][nb], a[mt], b[nb >> 1][(nb & 1) * 2], b[nb >> 1][(nb & 1) * 2 + 1]);
        }
        __syncthreads();       // all warps done with A(ch)/B32(ch) slots

        if (ch + 2 < NCH) issue_group(ch + 2);   // refill slot s (just freed)
        else cp_commit();                        // keep group count aligned
    }

    // epilogue: + bias, write fp32 projections (tile may span W matrices)
    const int qrow = lane >> 2;
    const int qcol = (lane & 3) * 2;
    #pragma unroll
    for (int mt = 0; mt < 2; mt++) {
        const int r = m0 + (wid & 3) * 32 + mt * 16 + qrow;
        #pragma unroll
        for (int nb = 0; nb < 6; nb++) {
            const int n  = ng + (wid >> 2) * 48 + nb * 8 + qcol;
            const int nw = n >> 9;
            const int no = n & 511;
            const float2 b2 = *(const float2*)&p.b[nw][no];
            float* d0 = &g_proj[((size_t)nw * MM + r) * DD + no];
            float* d1 = &g_proj[((size_t)nw * MM + r + 8) * DD + no];
            ((float2*)d0)[0] = {acc[mt][nb][0] + b2.x, acc[mt][nb][1] + b2.y};
            ((float2*)d1)[0] = {acc[mt][nb][2] + b2.x, acc[mt][nb][3] + b2.y};
        }
    }
}

// ---------------------------------------------------------------------------
// attn: bucketed-moment temporal softmax (R12 form, measured good)
// ---------------------------------------------------------------------------
__global__ __launch_bounds__(256) void attn_kernel(float* __restrict__ out) {
    const int m    = blockIdx.x;
    const int tid  = threadIdx.x;
    const int lane = tid & 31;
    const int wid  = tid >> 5;    // 8 warps
    const float LOG2E = 1.4426950408889634f;

    const float* __restrict__ Qf = g_proj + (size_t)0 * MM * DD + (size_t)m * DD;
    const float* __restrict__ Kf = g_proj + (size_t)1 * MM * DD + (size_t)m * DD;
    const float* __restrict__ Vf = g_proj + (size_t)2 * MM * DD + (size_t)m * DD;
    const float* __restrict__ Qt = g_proj + (size_t)3 * MM * DD + (size_t)m * DD;
    const float* __restrict__ Kt = g_proj + (size_t)4 * MM * DD + (size_t)m * DD;
    const float* __restrict__ Vt = g_proj + (size_t)5 * MM * DD + (size_t)m * DD;

    __shared__ __align__(16) float sK[DD];
    __shared__ __align__(16) float sV[DD];
    __shared__ float sMA[NB][8];
    __shared__ float sMM[NB][8];
    __shared__ float redA[8], redB[8], redC[8];

    const int i0 = tid, i1 = tid + 256;
    sK[i0] = Kt[i0]; sK[i1] = Kt[i1];
    sV[i0] = Vt[i0]; sV[i1] = Vt[i1];
    const float s0  = Qf[i0] * Kf[i0];
    const float s1  = Qf[i1] * Kf[i1];
    const float vf0 = Vf[i0], vf1 = Vf[i1];
    const float c0v = Qt[i0], c1v = Qt[i1];

    float smax = fmaxf(s0, s1), cmin = fminf(c0v, c1v), cmax = fmaxf(c0v, c1v);
    #pragma unroll
    for (int off = 16; off; off >>= 1) {
        smax = fmaxf(smax, __shfl_xor_sync(0xffffffffu, smax, off));
        cmin = fminf(cmin, __shfl_xor_sync(0xffffffffu, cmin, off));
        cmax = fmaxf(cmax, __shfl_xor_sync(0xffffffffu, cmax, off));
    }
    if (lane == 0) { redA[wid] = smax; redB[wid] = cmin; redC[wid] = cmax; }
    __syncthreads();
    smax = redA[0]; cmin = redB[0]; cmax = redC[0];
    #pragma unroll
    for (int t = 1; t < 8; t++) {
        smax = fmaxf(smax, redA[t]);
        cmin = fminf(cmin, redB[t]);
        cmax = fmaxf(cmax, redC[t]);
    }
    __syncthreads();

    const float e0 = ex2f((s0 - smax) * LOG2E);
    const float e1 = ex2f((s1 - smax) * LOG2E);
    float zf = e0 + e1;
    #pragma unroll
    for (int off = 16; off; off >>= 1)
        zf += __shfl_xor_sync(0xffffffffu, zf, off);
    if (lane == 0) redA[wid] = zf;
    __syncthreads();
    zf = redA[0];
    #pragma unroll
    for (int t = 1; t < 8; t++) zf += redA[t];
    const float ctx_f0 = (e0 / zf) * vf0;
    const float ctx_f1 = (e1 / zf) * vf1;

    const float bw = (cmax - cmin) * (1.0f / NB);
    const float c0 = fmaf((float)wid + 0.5f, bw, cmin);
    const float c0l = c0 * LOG2E;

    float a1[ND], m1[ND], a2[ND], m2[ND];
    #pragma unroll
    for (int n = 0; n < ND; n++) { a1[n] = 0.f; m1[n] = 0.f; a2[n] = 0.f; m2[n] = 0.f; }

    #pragma unroll
    for (int jj = 0; jj < DD / 64; jj++) {
        const int j = jj * 64 + lane;
        const float ka = sK[j],      va = sV[j];
        const float kb = sK[j + 32], vb = sV[j + 32];
        float pa = ex2f(c0l * ka);
        float pb = ex2f(c0l * kb);
        #pragma unroll
        for (int n = 0; n < ND; n++) {
            a1[n] += pa;
            a2[n] += pb;
            m1[n]  = fmaf(pa, va, m1[n]);
            m2[n]  = fmaf(pb, vb, m2[n]);
            if (n < ND - 1) { pa *= ka; pb *= kb; }
        }
    }
    #pragma unroll
    for (int n = 0; n < ND; n++) {
        float av = a1[n] + a2[n], mv = m1[n] + m2[n];
        #pragma unroll
        for (int off = 16; off; off >>= 1) {
            av += __shfl_xor_sync(0xffffffffu, av, off);
            mv += __shfl_xor_sync(0xffffffffu, mv, off);
        }
        if (lane == 0) { sMA[wid][n] = av; sMM[wid][n] = mv; }
    }
    __syncthreads();

    const float W  = cmax - cmin;
    const float sc = (W > 0.f) ? ((float)NB / W) : 0.f;
    const float IF[ND] = {1.f, 1.f, 0.5f, 1.f/6.f, 1.f/24.f, 1.f/120.f};

    #pragma unroll
    for (int item = 0; item < 2; item++) {
        const float c = item ? c1v : c0v;
        int b = (int)((c - cmin) * sc);
        b = (b > NB - 1) ? NB - 1 : ((b < 0) ? 0 : b);
        const float d = c - fmaf((float)b + 0.5f, bw, cmin);
        const float* MA  = sMA[b];
        const float* MMp = sMM[b];
        float den = MA[ND - 1] * IF[ND - 1];
        float num = MMp[ND - 1] * IF[ND - 1];
        #pragma unroll
        for (int n = ND - 2; n >= 0; n--) {
            den = fmaf(den, d, MA[n] * IF[n]);
            num = fmaf(num, d, MMp[n] * IF[n]);
        }
        const float ctx_f = item ? ctx_f1 : ctx_f0;
        out[(size_t)m * DD + (item ? i1 : i0)] = ctx_f + num / den;
    }
}

extern "C" void kernel_launch(void* const* d_in, const int* in_sizes, int n_in,
                              void* d_out, int out_size) {
    (void)in_sizes; (void)n_in; (void)out_size;
    const float* x = (const float*)d_in[0];
    WPtrs p;
    for (int w = 0; w < NWT; w++) {
        p.W[w] = (const float*)d_in[1 + 2 * w];
        p.b[w] = (const float*)d_in[2 + 2 * w];
    }
    cudaFuncSetAttribute(gemm_mma, cudaFuncAttributeMaxDynamicSharedMemorySize, GSMEM);
    conv_x<<<256, 256>>>(x);
    gemm_mma<<<dim3(MM / MT, NN / NT), 256, GSMEM>>>(p);
    attn_kernel<<<MM, 256>>>((float*)d_out);
}